// round 10
// baseline (speedup 1.0000x reference)
// R9: mask in cp.async pipeline; ex2.approx.f16x2 softmax; Q pre-scaled fp16.
#include <cuda_runtime.h>
#include <cuda_fp16.h>
#include <math.h>
#include <stdint.h>
#include <stddef.h>

#define BB 2
#define SS 2048
#define DD 192
#define HH 16
#define HDIM 128

typedef unsigned long long u64;
typedef unsigned int u32;

// ---- fp16 helpers ----
__device__ __forceinline__ u32 h2(float a, float b) {
    __half2 h = __floats2half2_rn(a, b);
    return *(u32*)&h;
}
__device__ __forceinline__ u32 hex2(u32 x) {      // packed exp2 on two halves
    u32 d; asm("ex2.approx.f16x2 %0, %1;" : "=r"(d) : "r"(x)); return d;
}
__device__ __forceinline__ void mma_f16(float d[4], u32 a0, u32 a1, u32 a2, u32 a3,
                                        u32 b0, u32 b1) {
    asm volatile(
        "mma.sync.aligned.m16n8k16.row.col.f32.f16.f16.f32 "
        "{%0,%1,%2,%3}, {%4,%5,%6,%7}, {%8,%9}, {%0,%1,%2,%3};\n"
        : "+f"(d[0]), "+f"(d[1]), "+f"(d[2]), "+f"(d[3])
        : "r"(a0), "r"(a1), "r"(a2), "r"(a3), "r"(b0), "r"(b1));
}
__device__ __forceinline__ u32 smem_u32(const void* p) {
    u32 a; asm("{.reg .u64 t; cvta.to.shared.u64 t, %1; cvt.u32.u64 %0, t;}" : "=r"(a) : "l"(p));
    return a;
}
__device__ __forceinline__ void cpa16(u32 dst, const void* src) {
    asm volatile("cp.async.cg.shared.global [%0], [%1], 16;" :: "r"(dst), "l"(src));
}
#define CPA_COMMIT() asm volatile("cp.async.commit_group;" ::: "memory")
#define CPA_WAIT1()  asm volatile("cp.async.wait_group 1;" ::: "memory")

// Scratch
__device__ float g_q[BB * HH * SS * HDIM];
__device__ float g_k[BB * HH * SS * HDIM];
__device__ float g_v[BB * HH * SS * HDIM];
__device__ __half g_qh[BB * HH * SS * HDIM];   // rope'd q, pre-scaled by s*log2e
__device__ __half g_kh[BB * HH * SS * HDIM];
__device__ __half g_vh[BB * HH * HDIM * SS];   // transposed: [b][h][d][s]
__device__ float g_attn[BB * SS * HH * HDIM];
__device__ float g_part[4][BB * SS * DD];
__device__ float g_cos[SS * 64];
__device__ float g_sin[SS * 64];

#define LOG2E 1.4426950408889634f
#define QSCALE2 (0.08838834764831845f * 1.4426950408889634f)
#define EOFF (4.0f * 1.4426950408889634f)

// ---------------------------------------------------------------------------
// Kernel 0: RoPE cos/sin table.
// ---------------------------------------------------------------------------
__global__ __launch_bounds__(256) void rope_init_kernel()
{
    int i = blockIdx.x * 256 + threadIdx.x;
    int s = i >> 6, p = i & 63;
    double inv = exp((double)p * -0.21586735246819178);
    double ang = fmod((double)s * inv, 6.283185307179586476925287);
    float a = (float)ang;
    g_cos[i] = cosf(a);
    g_sin[i] = sinf(a);
}

// ---------------------------------------------------------------------------
// Kernel 1: QKV projection, fp16 mma. grid (32, 32, 3), block 256.
// ---------------------------------------------------------------------------
#define QKV_SMEM ((128 * 100 + 64 * 100) * 4)

__global__ __launch_bounds__(256) void qkv_kernel(
    const float* __restrict__ x, const float* __restrict__ wq,
    const float* __restrict__ wk, const float* __restrict__ wv)
{
    extern __shared__ u32 qsm[];
    u32* sX = qsm;
    u32* sW = qsm + 128 * 100;
    const int tid = threadIdx.x;
    const int wid = tid >> 5, lane = tid & 31;
    const int g = lane >> 2, q4 = lane & 3;
    const int rw = wid & 3, cw = wid >> 2;
    const int m0 = blockIdx.x * 128;
    const int n0 = blockIdx.y * 64;
    const int z = blockIdx.z;
    const float* w = (z == 0) ? wq : (z == 1) ? wk : wv;
    float* dst = (z == 0) ? g_q : (z == 1) ? g_k : g_v;

    #pragma unroll
    for (int it = 0; it < 24; it++) {
        int idx = tid + it * 256;
        int r = idx / 48, l = idx % 48;
        float4 v = *(const float4*)&x[(size_t)(m0 + r) * 192 + 4 * l];
        sX[r * 100 + 2 * l] = h2(v.x, v.y);
        sX[r * 100 + 2 * l + 1] = h2(v.z, v.w);
    }
    #pragma unroll
    for (int it = 0; it < 12; it++) {
        int idx = tid + it * 256;
        int r = idx / 48, l = idx % 48;
        float4 v = *(const float4*)&w[(size_t)(n0 + r) * 192 + 4 * l];
        sW[r * 100 + 2 * l] = h2(v.x, v.y);
        sW[r * 100 + 2 * l + 1] = h2(v.z, v.w);
    }
    __syncthreads();

    float acc[2][4][4];
    #pragma unroll
    for (int mt = 0; mt < 2; mt++)
        #pragma unroll
        for (int nt = 0; nt < 4; nt++)
            #pragma unroll
            for (int c = 0; c < 4; c++) acc[mt][nt][c] = 0.0f;

    #pragma unroll
    for (int kk = 0; kk < 12; kk++) {
        u32 a[2][4];
        #pragma unroll
        for (int mt = 0; mt < 2; mt++) {
            int base = (32 * rw + 16 * mt + g) * 100 + 8 * kk + q4;
            a[mt][0] = sX[base];
            a[mt][1] = sX[base + 800];
            a[mt][2] = sX[base + 4];
            a[mt][3] = sX[base + 804];
        }
        #pragma unroll
        for (int nt = 0; nt < 4; nt++) {
            int nb = (32 * cw + 8 * nt + g) * 100 + 8 * kk + q4;
            u32 b0 = sW[nb], b1 = sW[nb + 4];
            mma_f16(acc[0][nt], a[0][0], a[0][1], a[0][2], a[0][3], b0, b1);
            mma_f16(acc[1][nt], a[1][0], a[1][1], a[1][2], a[1][3], b0, b1);
        }
    }

    #pragma unroll
    for (int mt = 0; mt < 2; mt++) {
        int mrow = m0 + 32 * rw + 16 * mt + g;
        int b_ = mrow >> 11, s_ = mrow & 2047;
        #pragma unroll
        for (int nt = 0; nt < 4; nt++) {
            int n = n0 + 32 * cw + 8 * nt + 2 * q4;
            int h_ = n >> 7, hd = n & 127;
            size_t o = ((size_t)(b_ * HH + h_) * SS + s_) * HDIM + hd;
            *(float2*)&dst[o] = make_float2(acc[mt][nt][0], acc[mt][nt][1]);
            *(float2*)&dst[o + 8 * HDIM] = make_float2(acc[mt][nt][2], acc[mt][nt][3]);
        }
    }
}

// ---------------------------------------------------------------------------
// Kernel 1b: V transpose+convert  g_v[b][h][s][d] f32 -> g_vh[b][h][d][s] f16.
// ---------------------------------------------------------------------------
__global__ __launch_bounds__(256) void vtrans_kernel()
{
    __shared__ float ts[64 * 65];
    const int tid = threadIdx.x;
    const int s0 = blockIdx.x * 64, d0 = blockIdx.y * 64;
    const size_t bh = (size_t)blockIdx.z;
    const float* src = g_v + bh * SS * HDIM;
    __half* dst = g_vh + bh * HDIM * SS;

    #pragma unroll
    for (int it = 0; it < 4; it++) {
        int idx = tid + it * 256;
        int r = idx >> 4, c = (idx & 15) * 4;
        float4 v = *(const float4*)&src[(size_t)(s0 + r) * HDIM + d0 + c];
        ts[(c + 0) * 65 + r] = v.x;
        ts[(c + 1) * 65 + r] = v.y;
        ts[(c + 2) * 65 + r] = v.z;
        ts[(c + 3) * 65 + r] = v.w;
    }
    __syncthreads();
    #pragma unroll
    for (int it = 0; it < 8; it++) {
        int idx = tid + it * 256;
        int r = idx >> 5, c = (idx & 31) * 2;
        __half2 h = __floats2half2_rn(ts[r * 65 + c], ts[r * 65 + c + 1]);
        *(__half2*)&dst[(size_t)(d0 + r) * SS + s0 + c] = h;
    }
}

// ---------------------------------------------------------------------------
// Kernel 2: RMSNorm + RoPE. q -> fp16 pre-scaled (g_qh), k -> fp16 (g_kh).
// ---------------------------------------------------------------------------
__global__ __launch_bounds__(128) void normrope_kernel(
    const float* __restrict__ qw, const float* __restrict__ kw)
{
    __shared__ float sq[128], sk[128], red[8];
    const int bs = blockIdx.x;
    const int h = bs & 15;
    const int s = (bs >> 4) & 2047;
    const int b = bs >> 15;
    const int hd = threadIdx.x;
    const size_t base = ((size_t)(b * HH + h) * SS + s) * HDIM + hd;

    float qv = g_q[base];
    float kv = g_k[base];
    float q2 = qv * qv, k2 = kv * kv;
    #pragma unroll
    for (int off = 16; off; off >>= 1) {
        q2 += __shfl_xor_sync(0xffffffffu, q2, off);
        k2 += __shfl_xor_sync(0xffffffffu, k2, off);
    }
    if ((hd & 31) == 0) { red[hd >> 5] = q2; red[4 + (hd >> 5)] = k2; }
    __syncthreads();
    float qs = red[0] + red[1] + red[2] + red[3];
    float ks = red[4] + red[5] + red[6] + red[7];
    float qr = rsqrtf(qs * (1.0f / 128.0f) + 1e-6f);
    float kr = rsqrtf(ks * (1.0f / 128.0f) + 1e-6f);
    float qn = qv * qr * qw[hd];
    float kn = kv * kr * kw[hd];
    sq[hd] = qn; sk[hd] = kn;
    __syncthreads();

    int p = hd & 63;
    float cs = g_cos[s * 64 + p];
    float sn = g_sin[s * 64 + p];
    float qrot = (hd < 64) ? -sq[hd + 64] : sq[hd - 64];
    float krot = (hd < 64) ? -sk[hd + 64] : sk[hd - 64];
    g_qh[base] = __float2half((qn * cs + qrot * sn) * QSCALE2);
    g_kh[base] = __float2half(kn * cs + krot * sn);
}

// ---------------------------------------------------------------------------
// Kernel 3: flash attention. cp.async double-buffers K, V, AND mask.
// grid (16, 16, 2), block 256 (8 warps).
// ---------------------------------------------------------------------------
#define SKB 0
#define SK_BYTES 17408                  // 64 * 68 u32
#define SVB (2 * SK_BYTES)              // 34816
#define SV_BYTES 18432                  // 128 * 36 u32
#define SMB (SVB + 2 * SV_BYTES)        // 71680
#define SM_BYTES 34816                  // 128 * 68 f32
#define SPB (SMB + 2 * SM_BYTES)        // 141312
#define SLB (SPB + 18432)               // 159744
#define AT_SMEM (SLB + 1024)            // 160768

__global__ __launch_bounds__(256, 1) void attn_kernel(const float* __restrict__ mask)
{
    extern __shared__ __align__(16) char smc[];
    u32* sP = (u32*)(smc + SPB);
    float* sL = (float*)(smc + SLB);
    const u32 sbase = smem_u32(smc);

    const int tid = threadIdx.x;
    const int wid = tid >> 5, lane = tid & 31;
    const int g = lane >> 2, q4 = lane & 3;
    const int rw = wid & 3, cw = wid >> 2;

    const int q0 = blockIdx.x * 128;
    const int h = blockIdx.y, b = blockIdx.z;
    const size_t bh = (size_t)(b * HH + h) * SS * HDIM;
    const __half* Qh = g_qh + bh;
    const __half* Kg = g_kh + bh;
    const __half* Vg = g_vh + bh;       // [d][s]
    const float* mbase = mask + (size_t)b * SS * SS;

    // per-thread cp.async slices
    const int krow = tid >> 2, kchunk = tid & 3;   // K: 64 rows, 4 thr/row
    const int vrow = tid >> 1, vchunk = tid & 1;   // V: 128 rows, 2 thr/row
    const int mrowi = tid >> 1, mchunk = tid & 1;  // M: 128 rows, 2 thr/row

    // Q fragments: direct u32 loads of pre-scaled fp16
    u32 qf[2][8][4];
    #pragma unroll
    for (int mt = 0; mt < 2; mt++)
        #pragma unroll
        for (int kk = 0; kk < 8; kk++) {
            const __half* qp = &Qh[(size_t)(q0 + 32 * rw + 16 * mt + g) * HDIM + 2 * q4 + 16 * kk];
            qf[mt][kk][0] = *(const u32*)qp;
            qf[mt][kk][1] = *(const u32*)(qp + 8 * HDIM);
            qf[mt][kk][2] = *(const u32*)(qp + 8);
            qf[mt][kk][3] = *(const u32*)(qp + 8 * HDIM + 8);
        }

    float o[2][8][4];
    #pragma unroll
    for (int mt = 0; mt < 2; mt++)
        #pragma unroll
        for (int nt = 0; nt < 8; nt++)
            #pragma unroll
            for (int c = 0; c < 4; c++) o[mt][nt][c] = 0.0f;
    float rsum[2][2] = {};

    // prefetch tile 0 into buffer 0
    {
        u32 kdst = sbase + SKB + krow * 272 + kchunk * 16;
        u32 vdst = sbase + SVB + vrow * 144 + vchunk * 16;
        u32 mdst = sbase + SMB + mrowi * 272;
        const float* msrc = &mbase[(size_t)(q0 + mrowi) * SS];
        #pragma unroll
        for (int it = 0; it < 4; it++)
            cpa16(kdst + it * 64, &Kg[(size_t)krow * HDIM + (kchunk + 4 * it) * 8]);
        #pragma unroll
        for (int it = 0; it < 4; it++)
            cpa16(vdst + it * 32, &Vg[(size_t)vrow * SS + (vchunk + 2 * it) * 8]);
        #pragma unroll
        for (int it = 0; it < 8; it++)
            cpa16(mdst + (mchunk + 2 * it) * 16, msrc + (mchunk + 2 * it) * 4);
    }
    CPA_COMMIT();

    for (int kt = 0; kt < 32; kt++) {
        const int k0 = kt * 64;
        const int bf = kt & 1;
        if (kt < 31) {
            const int k1 = k0 + 64;
            const int nbf = bf ^ 1;
            u32 kdst = sbase + SKB + nbf * SK_BYTES + krow * 272 + kchunk * 16;
            u32 vdst = sbase + SVB + nbf * SV_BYTES + vrow * 144 + vchunk * 16;
            u32 mdst = sbase + SMB + nbf * SM_BYTES + mrowi * 272;
            const float* msrc = &mbase[(size_t)(q0 + mrowi) * SS + k1];
            #pragma unroll
            for (int it = 0; it < 4; it++)
                cpa16(kdst + it * 64, &Kg[(size_t)(k1 + krow) * HDIM + (kchunk + 4 * it) * 8]);
            #pragma unroll
            for (int it = 0; it < 4; it++)
                cpa16(vdst + it * 32, &Vg[(size_t)vrow * SS + k1 + (vchunk + 2 * it) * 8]);
            #pragma unroll
            for (int it = 0; it < 8; it++)
                cpa16(mdst + (mchunk + 2 * it) * 16, msrc + (mchunk + 2 * it) * 4);
        }
        CPA_COMMIT();
        CPA_WAIT1();
        __syncthreads();   // tile kt resident; prior PV reads of sP done

        const u32* sK = (const u32*)(smc + SKB + bf * SK_BYTES);
        const u32* sV = (const u32*)(smc + SVB + bf * SV_BYTES);
        const float* sM = (const float*)(smc + SMB + bf * SM_BYTES);

        // QK^T (A = registers, B = sK)
        float acc[2][4][4];
        #pragma unroll
        for (int mt = 0; mt < 2; mt++)
            #pragma unroll
            for (int nt = 0; nt < 4; nt++)
                #pragma unroll
                for (int c = 0; c < 4; c++) acc[mt][nt][c] = 0.0f;
        #pragma unroll
        for (int kk = 0; kk < 8; kk++) {
            #pragma unroll
            for (int nt = 0; nt < 4; nt++) {
                int key = 32 * cw + 8 * nt + g;
                u32 b0 = sK[key * 68 + 8 * kk + q4];
                u32 b1 = sK[key * 68 + 8 * kk + q4 + 4];
                mma_f16(acc[0][nt], qf[0][kk][0], qf[0][kk][1], qf[0][kk][2], qf[0][kk][3], b0, b1);
                mma_f16(acc[1][nt], qf[1][kk][0], qf[1][kk][1], qf[1][kk][2], qf[1][kk][3], b0, b1);
            }
        }

        // softmax epilogue: packed ex2 on halves; mask from smem
        #pragma unroll
        for (int mt = 0; mt < 2; mt++) {
            int row0 = 32 * rw + 16 * mt + g;
            #pragma unroll
            for (int nt = 0; nt < 4; nt++) {
                const float* mp = &sM[row0 * 68 + 32 * cw + 8 * nt + 2 * q4];
                float2 m0 = *(const float2*)mp;
                float2 m1 = *(const float2*)(mp + 8 * 68);
                float t0 = acc[mt][nt][0] + m0.x * LOG2E - EOFF;
                float t1 = acc[mt][nt][1] + m0.y * LOG2E - EOFF;
                float t2 = acc[mt][nt][2] + m1.x * LOG2E - EOFF;
                float t3 = acc[mt][nt][3] + m1.y * LOG2E - EOFF;
                u32 p01 = hex2(h2(t0, t1));
                u32 p23 = hex2(h2(t2, t3));
                sP[row0 * 36 + 16 * cw + 4 * nt + q4] = p01;
                sP[(row0 + 8) * 36 + 16 * cw + 4 * nt + q4] = p23;
                float2 f0 = __half22float2(*(__half2*)&p01);
                float2 f1 = __half22float2(*(__half2*)&p23);
                rsum[mt][0] += f0.x + f0.y;
                rsum[mt][1] += f1.x + f1.y;
            }
        }
        __syncthreads();   // P complete

        // PV (A = sP, B = sV)
        #pragma unroll
        for (int kk = 0; kk < 4; kk++) {
            u32 a[2][4];
            #pragma unroll
            for (int mt = 0; mt < 2; mt++) {
                int row0 = 32 * rw + 16 * mt + g;
                a[mt][0] = sP[row0 * 36 + q4 + 8 * kk];
                a[mt][1] = sP[(row0 + 8) * 36 + q4 + 8 * kk];
                a[mt][2] = sP[row0 * 36 + q4 + 4 + 8 * kk];
                a[mt][3] = sP[(row0 + 8) * 36 + q4 + 4 + 8 * kk];
            }
            #pragma unroll
            for (int nt = 0; nt < 8; nt++) {
                int d = 64 * cw + 8 * nt + g;
                u32 b0 = sV[d * 36 + q4 + 8 * kk];
                u32 b1 = sV[d * 36 + q4 + 4 + 8 * kk];
                mma_f16(o[0][nt], a[0][0], a[0][1], a[0][2], a[0][3], b0, b1);
                mma_f16(o[1][nt], a[1][0], a[1][1], a[1][2], a[1][3], b0, b1);
            }
        }
    }

    // finalize
    #pragma unroll
    for (int mt = 0; mt < 2; mt++)
        #pragma unroll
        for (int half = 0; half < 2; half++) {
            float s = rsum[mt][half];
            s += __shfl_xor_sync(0xffffffffu, s, 1);
            s += __shfl_xor_sync(0xffffffffu, s, 2);
            rsum[mt][half] = s;
        }
    if (q4 == 0) {
        #pragma unroll
        for (int mt = 0; mt < 2; mt++) {
            sL[cw * 128 + 32 * rw + 16 * mt + g] = rsum[mt][0];
            sL[cw * 128 + 32 * rw + 16 * mt + g + 8] = rsum[mt][1];
        }
    }
    __syncthreads();

    #pragma unroll
    for (int mt = 0; mt < 2; mt++) {
        int row0 = 32 * rw + 16 * mt + g;
        float inv0 = 1.0f / (sL[row0] + sL[128 + row0]);
        float inv1 = 1.0f / (sL[row0 + 8] + sL[128 + row0 + 8]);
        #pragma unroll
        for (int nt = 0; nt < 8; nt++) {
            int d = 64 * cw + 8 * nt + 2 * q4;
            size_t ob0 = (size_t)(b * SS + q0 + row0) * (HH * HDIM) + h * HDIM + d;
            size_t ob1 = (size_t)(b * SS + q0 + row0 + 8) * (HH * HDIM) + h * HDIM + d;
            *(float2*)&g_attn[ob0] = make_float2(o[mt][nt][0] * inv0, o[mt][nt][1] * inv0);
            *(float2*)&g_attn[ob1] = make_float2(o[mt][nt][2] * inv1, o[mt][nt][3] * inv1);
        }
    }
}

// ---------------------------------------------------------------------------
// Kernel 4a: output projection, fp16 mma, split-K=4. grid (32, 3, 4).
// ---------------------------------------------------------------------------
__global__ __launch_bounds__(256) void oproj_part_kernel(const float* __restrict__ wo)
{
    __shared__ u32 sA[128 * 36];
    __shared__ u32 sB[64 * 36];
    const int tid = threadIdx.x;
    const int wid = tid >> 5, lane = tid & 31;
    const int g = lane >> 2, q4 = lane & 3;
    const int rw = wid & 3, cw = wid >> 2;
    const int m0 = blockIdx.x * 128;
    const int n0 = blockIdx.y * 64;
    const int kt = blockIdx.z;

    float acc[2][4][4];
    #pragma unroll
    for (int mt = 0; mt < 2; mt++)
        #pragma unroll
        for (int nt = 0; nt < 4; nt++)
            #pragma unroll
            for (int c = 0; c < 4; c++) acc[mt][nt][c] = 0.0f;

    for (int kb = kt * 512; kb < kt * 512 + 512; kb += 64) {
        __syncthreads();
        #pragma unroll
        for (int it = 0; it < 8; it++) {
            int idx = tid + it * 256;
            int r = idx >> 4, l = idx & 15;
            float4 v = *(const float4*)&g_attn[(size_t)(m0 + r) * 2048 + kb + 4 * l];
            sA[r * 36 + 2 * l] = h2(v.x, v.y);
            sA[r * 36 + 2 * l + 1] = h2(v.z, v.w);
        }
        #pragma unroll
        for (int it = 0; it < 4; it++) {
            int idx = tid + it * 256;
            int r = idx >> 4, l = idx & 15;
            float4 v = *(const float4*)&wo[(size_t)(n0 + r) * 2048 + kb + 4 * l];
            sB[r * 36 + 2 * l] = h2(v.x, v.y);
            sB[r * 36 + 2 * l + 1] = h2(v.z, v.w);
        }
        __syncthreads();
        #pragma unroll
        for (int kk = 0; kk < 4; kk++) {
            u32 a[2][4];
            #pragma unroll
            for (int mt = 0; mt < 2; mt++) {
                int base = (32 * rw + 16 * mt + g) * 36 + 8 * kk + q4;
                a[mt][0] = sA[base];
                a[mt][1] = sA[base + 288];
                a[mt][2] = sA[base + 4];
                a[mt][3] = sA[base + 292];
            }
            #pragma unroll
            for (int nt = 0; nt < 4; nt++) {
                int nb = (32 * cw + 8 * nt + g) * 36 + 8 * kk + q4;
                u32 b0 = sB[nb], b1 = sB[nb + 4];
                mma_f16(acc[0][nt], a[0][0], a[0][1], a[0][2], a[0][3], b0, b1);
                mma_f16(acc[1][nt], a[1][0], a[1][1], a[1][2], a[1][3], b0, b1);
            }
        }
    }

    #pragma unroll
    for (int mt = 0; mt < 2; mt++) {
        int mrow = m0 + 32 * rw + 16 * mt + g;
        #pragma unroll
        for (int nt = 0; nt < 4; nt++) {
            int n = n0 + 32 * cw + 8 * nt + 2 * q4;
            float* pp = &g_part[kt][(size_t)mrow * DD + n];
            *(float2*)pp = make_float2(acc[mt][nt][0], acc[mt][nt][1]);
            *(float2*)(pp + 8 * DD) = make_float2(acc[mt][nt][2], acc[mt][nt][3]);
        }
    }
}

__global__ __launch_bounds__(256) void oproj_reduce_kernel(float* __restrict__ out)
{
    int idx = blockIdx.x * 256 + threadIdx.x;
    if (idx < (BB * SS * DD) / 4) {
        float4 a = *(const float4*)&g_part[0][idx * 4];
        float4 b = *(const float4*)&g_part[1][idx * 4];
        float4 c = *(const float4*)&g_part[2][idx * 4];
        float4 d = *(const float4*)&g_part[3][idx * 4];
        *(float4*)&out[idx * 4] = make_float4(a.x + b.x + c.x + d.x, a.y + b.y + c.y + d.y,
                                              a.z + b.z + c.z + d.z, a.w + b.w + c.w + d.w);
    }
}

// ---------------------------------------------------------------------------
// Inputs: x, mask0, wq, wk, wv, wo, q_norm_w, k_norm_w
// ---------------------------------------------------------------------------
extern "C" void kernel_launch(void* const* d_in, const int* in_sizes, int n_in,
                              void* d_out, int out_size)
{
    const float* x     = (const float*)d_in[0];
    const float* mask0 = (const float*)d_in[1];
    const float* wq    = (const float*)d_in[2];
    const float* wk    = (const float*)d_in[3];
    const float* wv    = (const float*)d_in[4];
    const float* wo    = (const float*)d_in[5];
    const float* qnw   = (const float*)d_in[6];
    const float* knw   = (const float*)d_in[7];
    float* out = (float*)d_out;

    cudaFuncSetAttribute(qkv_kernel, cudaFuncAttributeMaxDynamicSharedMemorySize, QKV_SMEM);
    cudaFuncSetAttribute(attn_kernel, cudaFuncAttributeMaxDynamicSharedMemorySize, AT_SMEM);

    rope_init_kernel<<<SS * 64 / 256, 256>>>();
    qkv_kernel<<<dim3(32, 32, 3), 256, QKV_SMEM>>>(x, wq, wk, wv);
    vtrans_kernel<<<dim3(SS / 64, HDIM / 64, BB * HH), 256>>>();
    normrope_kernel<<<BB * SS * HH, 128>>>(qnw, knw);
    attn_kernel<<<dim3(SS / 128, HH, BB), 256, AT_SMEM>>>(mask0);
    oproj_part_kernel<<<dim3(32, 3, 4), 256>>>(wo);
    oproj_reduce_kernel<<<768, 256>>>(out);
}